// round 5
// baseline (speedup 1.0000x reference)
#include <cuda_runtime.h>
#include <math.h>
#include <stdint.h>

// Problem constants
#define Bb   64
#define NPG  400
#define Kk   250
#define Ff   64
#define LIN  16000
#define Hh   8000
#define Nn   (Bb*NPG)        // 25600
#define BN_EPS 1e-5f

// Scratch (device globals; no allocation allowed)
__device__ float g_xn[Bb*LIN];
__device__ int   g_selidx[Bb*Kk];
__device__ float g_stanh[Bb*Kk];
__device__ float g_hpart[10][Bb][Hh];   // split-K partials, 20.5 MB
__device__ float g_l2[Bb*4];            // gemm2 partial logits

// ---------------------------------------------------------------------------
// Kernel: fused scores + bitonic top-K; writes selected idx + tanh(score)
// ---------------------------------------------------------------------------
__global__ void k_sort(const float* __restrict__ feat, const float* __restrict__ w) {
    __shared__ float sv[512];
    __shared__ int   si[512];
    __shared__ float s_inv;
    int tid = threadIdx.x, b = blockIdx.x;
    int warp = tid >> 5, lane = tid & 31;

    if (tid == 0) {
        float s = 0.f;
        #pragma unroll
        for (int i = 0; i < Ff; i++) s += w[i] * w[i];
        s_inv = rsqrtf(s);
    }
    const float* xg = feat + (size_t)11 * Nn * Ff + (size_t)b * NPG * Ff;
    float wl0 = w[lane], wl1 = w[lane + 32];
    for (int nd = warp; nd < NPG; nd += 16) {
        const float* x = xg + (size_t)nd * Ff;
        float v = x[lane] * wl0 + x[lane + 32] * wl1;
        #pragma unroll
        for (int o = 16; o > 0; o >>= 1) v += __shfl_down_sync(0xffffffffu, v, o);
        if (lane == 0) sv[nd] = v;
    }
    if (tid >= NPG) sv[tid] = __int_as_float(0xff800000);
    si[tid] = tid;
    __syncthreads();

    // Bitonic sort: value descending, index ascending on ties
    for (int k = 2; k <= 512; k <<= 1) {
        for (int j = k >> 1; j > 0; j >>= 1) {
            int ixj = tid ^ j;
            if (ixj > tid) {
                float va = sv[tid], vb = sv[ixj];
                int   ia = si[tid], ib = si[ixj];
                bool aFirst = (va > vb) || (va == vb && ia < ib);
                bool bFirst = (vb > va) || (vb == va && ib < ia);
                bool desc = ((tid & k) == 0);
                bool sw = desc ? bFirst : aFirst;
                if (sw) { sv[tid] = vb; sv[ixj] = va; si[tid] = ib; si[ixj] = ia; }
            }
            __syncthreads();
        }
    }
    if (tid < Kk) {
        g_selidx[b * Kk + tid] = si[tid];
        g_stanh[b * Kk + tid]  = tanhf(sv[tid] * s_inv);
    }
}

// ---------------------------------------------------------------------------
// Kernel: gather + BatchNorm -> fp32 xn   grid (64, 4)
// ---------------------------------------------------------------------------
__global__ void k_bn(const float* __restrict__ feat,
                     const float* __restrict__ bn_mean, const float* __restrict__ bn_var,
                     const float* __restrict__ bn_gamma, const float* __restrict__ bn_beta) {
    int b = blockIdx.x, q = blockIdx.y, tid = threadIdx.x;
    const float* xg = feat + (size_t)11 * Nn * Ff + (size_t)b * NPG * Ff;
    int base = q * (LIN / 4);
    for (int t = tid; t < LIN / 4; t += 256) {
        int i = base + t;
        int r = i >> 6, f = i & 63;
        int idx = g_selidx[b * Kk + r];
        float st = g_stanh[b * Kk + r];
        float xv = xg[idx * Ff + f];
        float xn = (xv * st - bn_mean[i]) * rsqrtf(bn_var[i] + BN_EPS) * bn_gamma[i] + bn_beta[i];
        g_xn[(size_t)b * LIN + i] = xn;
    }
}

// ---------------------------------------------------------------------------
// GEMM1:  hpart[s][m][j] = sum_{k in chunk s} xn[m,k] * W1[j,k]
// tf32 mma.sync m16n8k8, fp32 smem via cp.async, fat 64x64 warp tiles.
// Block 256 thr (8 warps). BM=64, BN=512, BK=16. 3-stage ring, 1 CTA/SM.
// grid (16 j-blocks, KSPLIT=10) = 160 CTAs.
// ---------------------------------------------------------------------------
#define BN1    512
#define BK1    16
#define KSPLIT 10
#define KCHUNK (LIN / KSPLIT)    // 1600
#define ITERS  (KCHUNK / BK1)    // 100
#define NST    3
#define PADK   20                // floats per smem row (80B, conflict-free frags)
#define W_FLOATS (BN1 * PADK)    // 10240
#define X_FLOATS (64 * PADK)     // 1280
#define STG_FLOATS (W_FLOATS + X_FLOATS)      // 11520
#define SMEM1_BYTES (NST * STG_FLOATS * 4)    // 138240

__device__ __forceinline__ void mma_tf32(float* d, unsigned a0, unsigned a1,
                                         unsigned a2, unsigned a3,
                                         unsigned b0, unsigned b1) {
    asm volatile(
        "mma.sync.aligned.m16n8k8.row.col.f32.tf32.tf32.f32 "
        "{%0,%1,%2,%3}, {%4,%5,%6,%7}, {%8,%9}, {%0,%1,%2,%3};\n"
        : "+f"(d[0]), "+f"(d[1]), "+f"(d[2]), "+f"(d[3])
        : "r"(a0), "r"(a1), "r"(a2), "r"(a3), "r"(b0), "r"(b1));
}

__device__ __forceinline__ void cp16(unsigned smem_addr, const void* gptr) {
    asm volatile("cp.async.cg.shared.global [%0], [%1], 16;\n"
                 :: "r"(smem_addr), "l"(gptr));
}

__global__ __launch_bounds__(256, 1) void k_gemm1(const float* __restrict__ W1) {
    extern __shared__ float sm[];
    unsigned smbase = (unsigned)__cvta_generic_to_shared(sm);

    int tid  = threadIdx.x;
    int warp = tid >> 5, lane = tid & 31;
    int gi = lane >> 2, qi = lane & 3;
    int jbase = blockIdx.x * BN1;
    int kbase = blockIdx.y * KCHUNK;

    // cp.async mappings. W: 8 chunks/thread, chunk c: row=c>>2 (0..511), c4=c&3.
    const float* wsrc[8]; unsigned wdst[8];
    #pragma unroll
    for (int i = 0; i < 8; i++) {
        int c = tid + i * 256;
        int row = c >> 2, c4 = c & 3;
        int j = jbase + row; if (j > Hh - 1) j = Hh - 1;
        wsrc[i] = W1 + (size_t)j * LIN + kbase + c4 * 4;
        wdst[i] = smbase + (row * PADK + c4 * 4) * 4;
    }
    const float* xsrc; unsigned xdst;
    {
        int row = tid >> 2, c4 = tid & 3;
        xsrc = g_xn + (size_t)row * LIN + kbase + c4 * 4;
        xdst = smbase + (W_FLOATS + row * PADK + c4 * 4) * 4;
    }

    float acc[4][8][4];
    #pragma unroll
    for (int a = 0; a < 4; a++)
        #pragma unroll
        for (int b = 0; b < 8; b++)
            #pragma unroll
            for (int q = 0; q < 4; q++) acc[a][b][q] = 0.f;

    // prologue: stages 0, 1
    #pragma unroll
    for (int s = 0; s < NST - 1; s++) {
        unsigned so = (unsigned)(s * STG_FLOATS * 4);
        int ko = s * BK1;
        #pragma unroll
        for (int i = 0; i < 8; i++) cp16(wdst[i] + so, wsrc[i] + ko);
        cp16(xdst + so, xsrc + ko);
        asm volatile("cp.async.commit_group;\n");
    }

    for (int it = 0; it < ITERS; it++) {
        asm volatile("cp.async.wait_group 1;\n");
        __syncthreads();

        int st = it % NST;
        const float* sW = sm + st * STG_FLOATS;
        const float* sX = sW + W_FLOATS;

        #pragma unroll
        for (int ks = 0; ks < 2; ks++) {
            int k0 = ks * 8;
            unsigned a0[4], a1[4], a2[4], a3[4];
            #pragma unroll
            for (int mt = 0; mt < 4; mt++) {
                const float* ap = sX + (mt * 16 + gi) * PADK + k0 + qi;
                a0[mt] = __float_as_uint(ap[0]);
                a1[mt] = __float_as_uint(ap[8 * PADK]);
                a2[mt] = __float_as_uint(ap[4]);
                a3[mt] = __float_as_uint(ap[8 * PADK + 4]);
            }
            #pragma unroll
            for (int nt = 0; nt < 8; nt++) {
                const float* bp = sW + (warp * 64 + nt * 8 + gi) * PADK + k0 + qi;
                unsigned b0 = __float_as_uint(bp[0]);
                unsigned b1 = __float_as_uint(bp[4]);
                #pragma unroll
                for (int mt = 0; mt < 4; mt++)
                    mma_tf32(acc[mt][nt], a0[mt], a1[mt], a2[mt], a3[mt], b0, b1);
            }
        }

        // issue stage (it+2) — distinct from compute stage; overwritten stage
        // was last computed at it-1, protected by the top-of-iter barrier.
        int nk = it + NST - 1;
        if (nk < ITERS) {
            unsigned so = (unsigned)((nk % NST) * STG_FLOATS * 4);
            int ko = nk * BK1;
            #pragma unroll
            for (int i = 0; i < 8; i++) cp16(wdst[i] + so, wsrc[i] + ko);
            cp16(xdst + so, xsrc + ko);
        }
        asm volatile("cp.async.commit_group;\n");
    }

    // epilogue: plain coalesced-ish STG.64 into split-private partials
    float* hp = &g_hpart[blockIdx.y][0][0];
    #pragma unroll
    for (int mt = 0; mt < 4; mt++) {
        #pragma unroll
        for (int nt = 0; nt < 8; nt++) {
            int m0 = mt * 16 + gi;
            int j = jbase + warp * 64 + nt * 8 + qi * 2;
            if (j < Hh) {
                float2 v0 = make_float2(acc[mt][nt][0], acc[mt][nt][1]);
                float2 v1 = make_float2(acc[mt][nt][2], acc[mt][nt][3]);
                *(float2*)(hp + (size_t)m0 * Hh + j)       = v0;
                *(float2*)(hp + (size_t)(m0 + 8) * Hh + j) = v1;
            }
        }
    }
}

// ---------------------------------------------------------------------------
// GEMM2 + split-reduce + bias + relu.  grid (64, 4), 256 thr.
// logits partial: l2[m][q] = sum_{j in quarter q} relu(sum_s hpart[s][m][j] + b1[j]) * W2[j]
// ---------------------------------------------------------------------------
__global__ void k_gemm2(const float* __restrict__ b1, const float* __restrict__ W2) {
    int m = blockIdx.x, q = blockIdx.y, tid = threadIdx.x;
    int jq = q * (Hh / 4);
    float s = 0.f;
    for (int t = tid * 4; t < Hh / 4; t += 1024) {
        int j = jq + t;
        float4 hs = make_float4(0.f, 0.f, 0.f, 0.f);
        #pragma unroll
        for (int sp = 0; sp < KSPLIT; sp++) {
            float4 hv = *(const float4*)(&g_hpart[sp][m][j]);
            hs.x += hv.x; hs.y += hv.y; hs.z += hv.z; hs.w += hv.w;
        }
        float4 bv = *(const float4*)(b1 + j);
        float4 wv = *(const float4*)(W2 + j);
        s += fmaxf(hs.x + bv.x, 0.f) * wv.x;
        s += fmaxf(hs.y + bv.y, 0.f) * wv.y;
        s += fmaxf(hs.z + bv.z, 0.f) * wv.z;
        s += fmaxf(hs.w + bv.w, 0.f) * wv.w;
    }
    #pragma unroll
    for (int o = 16; o > 0; o >>= 1) s += __shfl_down_sync(0xffffffffu, s, o);
    __shared__ float red[8];
    if ((tid & 31) == 0) red[tid >> 5] = s;
    __syncthreads();
    if (tid < 8) {
        s = red[tid];
        #pragma unroll
        for (int o = 4; o > 0; o >>= 1) s += __shfl_down_sync(0xffu, s, o);
        if (tid == 0) g_l2[m * 4 + q] = s;
    }
}

// ---------------------------------------------------------------------------
// Loss: logits[m] = sum_q l2[m][q] + b2;  out = mean(softplus(l) - l)
// ---------------------------------------------------------------------------
__global__ void k_loss(const float* __restrict__ b2, float* __restrict__ out) {
    int tid = threadIdx.x;  // 64 threads
    float l = g_l2[tid * 4] + g_l2[tid * 4 + 1] + g_l2[tid * 4 + 2] + g_l2[tid * 4 + 3] + b2[0];
    float per = (l > 0.f) ? log1pf(expf(-l)) : (log1pf(expf(l)) - l);
    #pragma unroll
    for (int o = 16; o > 0; o >>= 1) per += __shfl_down_sync(0xffffffffu, per, o);
    __shared__ float r2[2];
    if ((tid & 31) == 0) r2[tid >> 5] = per;
    __syncthreads();
    if (tid == 0) out[0] = (r2[0] + r2[1]) * (1.0f / Bb);
}

// ---------------------------------------------------------------------------
extern "C" void kernel_launch(void* const* d_in, const int* in_sizes, int n_in,
                              void* d_out, int out_size) {
    const float* feat     = (const float*)d_in[0];
    const float* w        = (const float*)d_in[3];
    const float* bn_gamma = (const float*)d_in[4];
    const float* bn_beta  = (const float*)d_in[5];
    const float* bn_mean  = (const float*)d_in[6];
    const float* bn_var   = (const float*)d_in[7];
    const float* W1       = (const float*)d_in[8];
    const float* b1       = (const float*)d_in[9];
    const float* W2       = (const float*)d_in[10];
    const float* b2       = (const float*)d_in[11];

    cudaFuncSetAttribute(k_gemm1, cudaFuncAttributeMaxDynamicSharedMemorySize, SMEM1_BYTES);

    k_sort<<<Bb, 512>>>(feat, w);
    dim3 gbn(Bb, 4);
    k_bn<<<gbn, 256>>>(feat, bn_mean, bn_var, bn_gamma, bn_beta);
    dim3 g1(16, KSPLIT);   // 16 j-blocks x 10 k-splits = 160 CTAs
    k_gemm1<<<g1, 256, SMEM1_BYTES>>>(W1);
    dim3 g2(Bb, 4);
    k_gemm2<<<g2, 256>>>(b1, W2);
    k_loss<<<1, 64>>>(b2, (float*)d_out);
}

// round 6
// speedup vs baseline: 1.2144x; 1.2144x over previous
#include <cuda_runtime.h>
#include <math.h>
#include <stdint.h>

// Problem constants
#define Bb   64
#define NPG  400
#define Kk   250
#define Ff   64
#define LIN  16000
#define Hh   8000
#define Nn   (Bb*NPG)        // 25600
#define BN_EPS 1e-5f

#define KSPLIT 4

// Scratch (device globals; no allocation allowed)
__device__ float g_xn[Bb*LIN];
__device__ int   g_selidx[Bb*Kk];
__device__ float g_stanh[Bb*Kk];
__device__ float g_hpart[KSPLIT][Bb][Hh];   // split-K partials
__device__ float g_l2[Bb*4];                // gemm2 partial logits

// ---------------------------------------------------------------------------
// PTX helpers
// ---------------------------------------------------------------------------
#define MBAR_INIT(addr, cnt) \
    asm volatile("mbarrier.init.shared.b64 [%0], %1;" :: "r"(addr), "r"(cnt) : "memory")

#define MBAR_WAIT(addr, ph) do { \
    unsigned _done = 0; \
    while (!_done) { \
        asm volatile("{\n\t.reg .pred p;\n\t" \
                     "mbarrier.try_wait.parity.acquire.cta.shared::cta.b64 p, [%1], %2;\n\t" \
                     "selp.b32 %0, 1, 0, p;\n\t}" \
                     : "=r"(_done) : "r"(addr), "r"(ph) : "memory"); \
    } } while (0)

#define MBAR_EXPECT(addr, bytes) \
    asm volatile("mbarrier.arrive.expect_tx.shared.b64 _, [%0], %1;" \
                 :: "r"(addr), "r"(bytes) : "memory")

__device__ __forceinline__ void bulk_g2s(unsigned dst, const void* src,
                                         unsigned bytes, unsigned mbar) {
    asm volatile("cp.async.bulk.shared::cluster.global.mbarrier::complete_tx::bytes "
                 "[%0], [%1], %2, [%3];"
                 :: "r"(dst), "l"(src), "r"(bytes), "r"(mbar) : "memory");
}

#define FENCE_ASYNC() asm volatile("fence.proxy.async.shared::cta;" ::: "memory")

__device__ __forceinline__ void mma_tf32(float* d, unsigned a0, unsigned a1,
                                         unsigned a2, unsigned a3,
                                         unsigned b0, unsigned b1) {
    asm volatile(
        "mma.sync.aligned.m16n8k8.row.col.f32.tf32.tf32.f32 "
        "{%0,%1,%2,%3}, {%4,%5,%6,%7}, {%8,%9}, {%0,%1,%2,%3};\n"
        : "+f"(d[0]), "+f"(d[1]), "+f"(d[2]), "+f"(d[3])
        : "r"(a0), "r"(a1), "r"(a2), "r"(a3), "r"(b0), "r"(b1));
}

// ---------------------------------------------------------------------------
// Kernel: fused scores + bitonic top-K; writes selected idx + tanh(score)
// ---------------------------------------------------------------------------
__global__ void k_sort(const float* __restrict__ feat, const float* __restrict__ w) {
    __shared__ float sv[512];
    __shared__ int   si[512];
    __shared__ float s_inv;
    int tid = threadIdx.x, b = blockIdx.x;
    int warp = tid >> 5, lane = tid & 31;

    if (tid == 0) {
        float s = 0.f;
        #pragma unroll
        for (int i = 0; i < Ff; i++) s += w[i] * w[i];
        s_inv = rsqrtf(s);
    }
    const float* xg = feat + (size_t)11 * Nn * Ff + (size_t)b * NPG * Ff;
    float wl0 = w[lane], wl1 = w[lane + 32];
    for (int nd = warp; nd < NPG; nd += 16) {
        const float* x = xg + (size_t)nd * Ff;
        float v = x[lane] * wl0 + x[lane + 32] * wl1;
        #pragma unroll
        for (int o = 16; o > 0; o >>= 1) v += __shfl_down_sync(0xffffffffu, v, o);
        if (lane == 0) sv[nd] = v;
    }
    if (tid >= NPG) sv[tid] = __int_as_float(0xff800000);
    si[tid] = tid;
    __syncthreads();

    for (int k = 2; k <= 512; k <<= 1) {
        for (int j = k >> 1; j > 0; j >>= 1) {
            int ixj = tid ^ j;
            if (ixj > tid) {
                float va = sv[tid], vb = sv[ixj];
                int   ia = si[tid], ib = si[ixj];
                bool aFirst = (va > vb) || (va == vb && ia < ib);
                bool bFirst = (vb > va) || (vb == va && ib < ia);
                bool desc = ((tid & k) == 0);
                bool sw = desc ? bFirst : aFirst;
                if (sw) { sv[tid] = vb; sv[ixj] = va; si[tid] = ib; si[ixj] = ia; }
            }
            __syncthreads();
        }
    }
    if (tid < Kk) {
        g_selidx[b * Kk + tid] = si[tid];
        g_stanh[b * Kk + tid]  = tanhf(sv[tid] * s_inv);
    }
}

// ---------------------------------------------------------------------------
// Kernel: gather + BatchNorm -> fp32 xn   grid (64, 4)
// ---------------------------------------------------------------------------
__global__ void k_bn(const float* __restrict__ feat,
                     const float* __restrict__ bn_mean, const float* __restrict__ bn_var,
                     const float* __restrict__ bn_gamma, const float* __restrict__ bn_beta) {
    int b = blockIdx.x, q = blockIdx.y, tid = threadIdx.x;
    const float* xg = feat + (size_t)11 * Nn * Ff + (size_t)b * NPG * Ff;
    int base = q * (LIN / 4);
    for (int t = tid; t < LIN / 4; t += 256) {
        int i = base + t;
        int r = i >> 6, f = i & 63;
        int idx = g_selidx[b * Kk + r];
        float st = g_stanh[b * Kk + r];
        float xv = xg[idx * Ff + f];
        float xn = (xv * st - bn_mean[i]) * rsqrtf(bn_var[i] + BN_EPS) * bn_gamma[i] + bn_beta[i];
        g_xn[(size_t)b * LIN + i] = xn;
    }
}

// ---------------------------------------------------------------------------
// GEMM1:  hpart[s][m][j] = sum_{k in chunk s} xn[m,k] * W1[j,k]
// Loads via cp.async.bulk (UBLKCP, 128B per row) -> 4-stage mbarrier ring.
// tf32 mma.sync m16n8k8, warp tile 32m x 32j. 2 CTAs/SM, grid (63, KSPLIT).
// ---------------------------------------------------------------------------
#define BN1    128
#define BK1    32
#define KCHUNK (LIN / KSPLIT)    // 4000
#define ITERS  (KCHUNK / BK1)    // 125
#define NST    4
#define PADK   36                // floats per row (144B; bulk dst 16B aligned ok)
#define ROWB   (PADK * 4)        // 144 bytes
#define W_FLOATS (BN1 * PADK)    // 4608
#define X_FLOATS (64 * PADK)     // 2304
#define STG_FLOATS (W_FLOATS + X_FLOATS)         // 6912
#define STG_BYTES  (STG_FLOATS * 4)              // 27648
#define SMEM_MAIN  (NST * STG_BYTES)             // 110592
#define SMEM1_BYTES (SMEM_MAIN + 128)
#define TX_BYTES   (192 * 128)                   // 24576 per stage

__global__ __launch_bounds__(256, 2) void k_gemm1(const float* __restrict__ W1) {
    extern __shared__ __align__(128) float sm[];
    unsigned smbase = (unsigned)__cvta_generic_to_shared(sm);
    unsigned mbar0 = smbase + SMEM_MAIN;  // 4 mbarriers, 8B each

    int tid  = threadIdx.x;
    int warp = tid >> 5, lane = tid & 31;
    int wm = warp >> 2, wj = warp & 3;
    int gi = lane >> 2, qi = lane & 3;
    int jbase = blockIdx.x * BN1;
    int kbase = blockIdx.y * KCHUNK;

    if (tid == 0) {
        #pragma unroll
        for (int s = 0; s < NST; s++) MBAR_INIT(mbar0 + 8 * s, 192);
    }
    __syncthreads();

    // Per-thread bulk-load assignment: tid<128 -> W row tid; tid in [128,192) -> X row
    const float* lsrc = 0;
    unsigned     ldst = 0;
    bool loader = (tid < 192);
    if (tid < 128) {
        int j = jbase + tid; if (j > Hh - 1) j = Hh - 1;
        lsrc = W1 + (size_t)j * LIN + kbase;
        ldst = smbase + (unsigned)tid * ROWB;
    } else if (tid < 192) {
        int m = tid - 128;
        lsrc = g_xn + (size_t)m * LIN + kbase;
        ldst = smbase + (unsigned)(W_FLOATS * 4) + (unsigned)m * ROWB;
    }

    // prologue: fill all NST stages
    if (loader) {
        #pragma unroll
        for (int s = 0; s < NST; s++) {
            MBAR_EXPECT(mbar0 + 8 * s, 128);
            bulk_g2s(ldst + s * STG_BYTES, lsrc + s * BK1, 128, mbar0 + 8 * s);
        }
    }

    float acc[2][4][4];
    #pragma unroll
    for (int a = 0; a < 2; a++)
        #pragma unroll
        for (int b = 0; b < 4; b++)
            #pragma unroll
            for (int q = 0; q < 4; q++) acc[a][b][q] = 0.f;

    for (int it = 0; it < ITERS; it++) {
        int st = it & (NST - 1);
        unsigned ph = (unsigned)(it / NST) & 1u;
        MBAR_WAIT(mbar0 + 8 * st, ph);

        const float* sW = sm + st * STG_FLOATS;
        const float* sX = sW + W_FLOATS;

        #pragma unroll
        for (int ks = 0; ks < 4; ks++) {
            int k0 = ks * 8;
            unsigned a0[2], a1[2], a2[2], a3[2];
            #pragma unroll
            for (int mt = 0; mt < 2; mt++) {
                const float* ap = sX + (wm * 32 + mt * 16 + gi) * PADK + k0 + qi;
                a0[mt] = __float_as_uint(ap[0]);
                a1[mt] = __float_as_uint(ap[8 * PADK]);
                a2[mt] = __float_as_uint(ap[4]);
                a3[mt] = __float_as_uint(ap[8 * PADK + 4]);
            }
            #pragma unroll
            for (int nt = 0; nt < 4; nt++) {
                const float* bp = sW + (wj * 32 + nt * 8 + gi) * PADK + k0 + qi;
                unsigned b0 = __float_as_uint(bp[0]);
                unsigned b1 = __float_as_uint(bp[4]);
                #pragma unroll
                for (int mt = 0; mt < 2; mt++)
                    mma_tf32(acc[mt][nt], a0[mt], a1[mt], a2[mt], a3[mt], b0, b1);
            }
        }
        __syncthreads();   // all threads done reading stage st

        int nx = it + NST;
        if (nx < ITERS && loader) {
            FENCE_ASYNC();
            MBAR_EXPECT(mbar0 + 8 * st, 128);
            bulk_g2s(ldst + st * STG_BYTES, lsrc + nx * BK1, 128, mbar0 + 8 * st);
        }
    }

    // epilogue: plain STG into split-private partials
    float* hp = &g_hpart[blockIdx.y][0][0];
    #pragma unroll
    for (int mt = 0; mt < 2; mt++) {
        #pragma unroll
        for (int nt = 0; nt < 4; nt++) {
            int m = wm * 32 + mt * 16 + gi;
            int j = jbase + wj * 32 + nt * 8 + qi * 2;
            if (j < Hh) {
                *(float2*)(hp + (size_t)m * Hh + j) =
                    make_float2(acc[mt][nt][0], acc[mt][nt][1]);
                *(float2*)(hp + (size_t)(m + 8) * Hh + j) =
                    make_float2(acc[mt][nt][2], acc[mt][nt][3]);
            }
        }
    }
}

// ---------------------------------------------------------------------------
// GEMM2 + split-reduce + bias + relu.  grid (64, 4), 256 thr.
// ---------------------------------------------------------------------------
__global__ void k_gemm2(const float* __restrict__ b1, const float* __restrict__ W2) {
    int m = blockIdx.x, q = blockIdx.y, tid = threadIdx.x;
    int jq = q * (Hh / 4);
    float s = 0.f;
    for (int t = tid * 4; t < Hh / 4; t += 1024) {
        int j = jq + t;
        float4 hs = make_float4(0.f, 0.f, 0.f, 0.f);
        #pragma unroll
        for (int sp = 0; sp < KSPLIT; sp++) {
            float4 hv = *(const float4*)(&g_hpart[sp][m][j]);
            hs.x += hv.x; hs.y += hv.y; hs.z += hv.z; hs.w += hv.w;
        }
        float4 bv = *(const float4*)(b1 + j);
        float4 wv = *(const float4*)(W2 + j);
        s += fmaxf(hs.x + bv.x, 0.f) * wv.x;
        s += fmaxf(hs.y + bv.y, 0.f) * wv.y;
        s += fmaxf(hs.z + bv.z, 0.f) * wv.z;
        s += fmaxf(hs.w + bv.w, 0.f) * wv.w;
    }
    #pragma unroll
    for (int o = 16; o > 0; o >>= 1) s += __shfl_down_sync(0xffffffffu, s, o);
    __shared__ float red[8];
    if ((tid & 31) == 0) red[tid >> 5] = s;
    __syncthreads();
    if (tid < 8) {
        s = red[tid];
        #pragma unroll
        for (int o = 4; o > 0; o >>= 1) s += __shfl_down_sync(0xffu, s, o);
        if (tid == 0) g_l2[m * 4 + q] = s;
    }
}

// ---------------------------------------------------------------------------
// Loss
// ---------------------------------------------------------------------------
__global__ void k_loss(const float* __restrict__ b2, float* __restrict__ out) {
    int tid = threadIdx.x;  // 64 threads
    float l = g_l2[tid * 4] + g_l2[tid * 4 + 1] + g_l2[tid * 4 + 2] + g_l2[tid * 4 + 3] + b2[0];
    float per = (l > 0.f) ? log1pf(expf(-l)) : (log1pf(expf(l)) - l);
    #pragma unroll
    for (int o = 16; o > 0; o >>= 1) per += __shfl_down_sync(0xffffffffu, per, o);
    __shared__ float r2[2];
    if ((tid & 31) == 0) r2[tid >> 5] = per;
    __syncthreads();
    if (tid == 0) out[0] = (r2[0] + r2[1]) * (1.0f / Bb);
}

// ---------------------------------------------------------------------------
extern "C" void kernel_launch(void* const* d_in, const int* in_sizes, int n_in,
                              void* d_out, int out_size) {
    const float* feat     = (const float*)d_in[0];
    const float* w        = (const float*)d_in[3];
    const float* bn_gamma = (const float*)d_in[4];
    const float* bn_beta  = (const float*)d_in[5];
    const float* bn_mean  = (const float*)d_in[6];
    const float* bn_var   = (const float*)d_in[7];
    const float* W1       = (const float*)d_in[8];
    const float* b1       = (const float*)d_in[9];
    const float* W2       = (const float*)d_in[10];
    const float* b2       = (const float*)d_in[11];

    cudaFuncSetAttribute(k_gemm1, cudaFuncAttributeMaxDynamicSharedMemorySize, SMEM1_BYTES);

    k_sort<<<Bb, 512>>>(feat, w);
    dim3 gbn(Bb, 4);
    k_bn<<<gbn, 256>>>(feat, bn_mean, bn_var, bn_gamma, bn_beta);
    dim3 g1(63, KSPLIT);   // 63 j-blocks x 4 k-splits = 252 CTAs, 2/SM
    k_gemm1<<<g1, 256, SMEM1_BYTES>>>(W1);
    dim3 g2(Bb, 4);
    k_gemm2<<<g2, 256>>>(b1, W2);
    k_loss<<<1, 64>>>(b2, (float*)d_out);
}

// round 7
// speedup vs baseline: 1.6246x; 1.3378x over previous
#include <cuda_runtime.h>
#include <cuda_bf16.h>
#include <math.h>
#include <stdint.h>

// Problem constants
#define Bb   64
#define NPG  400
#define Kk   250
#define Ff   64
#define LIN  16000
#define Hh   8000
#define Nn   (Bb*NPG)        // 25600
#define BN_EPS 1e-5f

#define KSPLIT 7
#define KCH    2288          // 6 chunks of 2288 + 1 of 2272 = 16000

// Scratch (device globals; no allocation allowed)
__device__ __nv_bfloat16 g_xb[Bb*LIN];      // bf16 normalized features
__device__ int   g_selidx[Bb*Kk];
__device__ float g_stanh[Bb*Kk];
__device__ float g_hpart[KSPLIT][Bb][Hh];   // split-K partials
__device__ float g_l2[Bb*4];                // gemm2 partial logits

// ---------------------------------------------------------------------------
// Kernel: fused scores + bitonic top-K; writes selected idx + tanh(score)
// ---------------------------------------------------------------------------
__global__ void k_sort(const float* __restrict__ feat, const float* __restrict__ w) {
    __shared__ float sv[512];
    __shared__ int   si[512];
    __shared__ float s_inv;
    int tid = threadIdx.x, b = blockIdx.x;
    int warp = tid >> 5, lane = tid & 31;

    if (tid == 0) {
        float s = 0.f;
        #pragma unroll
        for (int i = 0; i < Ff; i++) s += w[i] * w[i];
        s_inv = rsqrtf(s);
    }
    const float* xg = feat + (size_t)11 * Nn * Ff + (size_t)b * NPG * Ff;
    float wl0 = w[lane], wl1 = w[lane + 32];
    for (int nd = warp; nd < NPG; nd += 16) {
        const float* x = xg + (size_t)nd * Ff;
        float v = x[lane] * wl0 + x[lane + 32] * wl1;
        #pragma unroll
        for (int o = 16; o > 0; o >>= 1) v += __shfl_down_sync(0xffffffffu, v, o);
        if (lane == 0) sv[nd] = v;
    }
    if (tid >= NPG) sv[tid] = __int_as_float(0xff800000);
    si[tid] = tid;
    __syncthreads();

    for (int k = 2; k <= 512; k <<= 1) {
        for (int j = k >> 1; j > 0; j >>= 1) {
            int ixj = tid ^ j;
            if (ixj > tid) {
                float va = sv[tid], vb = sv[ixj];
                int   ia = si[tid], ib = si[ixj];
                bool aFirst = (va > vb) || (va == vb && ia < ib);
                bool bFirst = (vb > va) || (vb == va && ib < ia);
                bool desc = ((tid & k) == 0);
                bool sw = desc ? bFirst : aFirst;
                if (sw) { sv[tid] = vb; sv[ixj] = va; si[tid] = ib; si[ixj] = ia; }
            }
            __syncthreads();
        }
    }
    if (tid < Kk) {
        g_selidx[b * Kk + tid] = si[tid];
        g_stanh[b * Kk + tid]  = tanhf(sv[tid] * s_inv);
    }
}

// ---------------------------------------------------------------------------
// Kernel: gather + BatchNorm -> bf16 xn   grid (64, 4)
// ---------------------------------------------------------------------------
__global__ void k_bn(const float* __restrict__ feat,
                     const float* __restrict__ bn_mean, const float* __restrict__ bn_var,
                     const float* __restrict__ bn_gamma, const float* __restrict__ bn_beta) {
    int b = blockIdx.x, q = blockIdx.y, tid = threadIdx.x;
    const float* xg = feat + (size_t)11 * Nn * Ff + (size_t)b * NPG * Ff;
    int base = q * (LIN / 4);
    for (int t = tid; t < LIN / 4; t += 256) {
        int i = base + t;
        int r = i >> 6, f = i & 63;
        int idx = g_selidx[b * Kk + r];
        float st = g_stanh[b * Kk + r];
        float xv = xg[idx * Ff + f];
        float xn = (xv * st - bn_mean[i]) * rsqrtf(bn_var[i] + BN_EPS) * bn_gamma[i] + bn_beta[i];
        g_xb[(size_t)b * LIN + i] = __float2bfloat16(xn);
    }
}

// ---------------------------------------------------------------------------
// GEMM1:  hpart[s][m][j] = sum_{k in chunk s} xn[m,k] * W1[j,k]
// bf16 mma.sync m16n8k16, W fp32->bf16 in-register, ldmatrix fragments.
// Block 256 thr (8 warps), warp tile 32m x 32j, BK=16, 2-stage smem,
// 3 CTAs/SM (launch_bounds 256,3). grid (63, 7) = 441 CTAs = one wave.
// ---------------------------------------------------------------------------
#define BN1   128
#define BK1   16
#define PADH  24                    // halves per smem row (48 B)
#define W_BYTES (128 * 48)          // 6144
#define X_BYTES (64 * 48)           // 3072
#define STG_B   (W_BYTES + X_BYTES) // 9216

__device__ __forceinline__ void mma16816(float* d,
                                         unsigned a0, unsigned a1, unsigned a2, unsigned a3,
                                         unsigned b0, unsigned b1) {
    asm volatile(
        "mma.sync.aligned.m16n8k16.row.col.f32.bf16.bf16.f32 "
        "{%0,%1,%2,%3}, {%4,%5,%6,%7}, {%8,%9}, {%0,%1,%2,%3};\n"
        : "+f"(d[0]), "+f"(d[1]), "+f"(d[2]), "+f"(d[3])
        : "r"(a0), "r"(a1), "r"(a2), "r"(a3), "r"(b0), "r"(b1));
}

__device__ __forceinline__ void ldsm4(unsigned& r0, unsigned& r1, unsigned& r2, unsigned& r3,
                                      unsigned addr) {
    asm volatile("ldmatrix.sync.aligned.m8n8.x4.shared.b16 {%0,%1,%2,%3}, [%4];"
                 : "=r"(r0), "=r"(r1), "=r"(r2), "=r"(r3) : "r"(addr));
}

__global__ __launch_bounds__(256, 3) void k_gemm1(const float* __restrict__ W1) {
    __shared__ __align__(16) unsigned char sm[2 * STG_B];
    unsigned smbase = (unsigned)__cvta_generic_to_shared(sm);

    int tid  = threadIdx.x;
    int warp = tid >> 5, lane = tid & 31;
    int wm = warp >> 2, wj = warp & 3;
    int gi = lane >> 2, qi = lane & 3;
    int jbase = blockIdx.x * BN1;
    int kbase = blockIdx.y * KCH;
    int iters = (blockIdx.y == KSPLIT - 1) ? 142 : 143;   // 142*16=2272, 143*16=2288

    // W load mapping: 2 float4/thread. chunk c: row=c>>2 (0..127), c4=c&3
    const float* wsrc[2]; unsigned wdst[2];
    #pragma unroll
    for (int i = 0; i < 2; i++) {
        int c = tid + i * 256;
        int row = c >> 2, c4 = c & 3;
        int j = jbase + row; if (j > Hh - 1) j = Hh - 1;
        wsrc[i] = W1 + (size_t)j * LIN + kbase + c4 * 4;
        wdst[i] = smbase + row * 48 + c4 * 8;
    }
    // X load mapping: threads 0..127, 1 uint4 (8 halves). row=tid>>1, seg=tid&1
    const __nv_bfloat16* xsrc = 0; unsigned xdst = 0;
    bool xload = (tid < 128);
    if (xload) {
        int row = tid >> 1, seg = tid & 1;
        xsrc = g_xb + (size_t)row * LIN + kbase + seg * 8;
        xdst = smbase + W_BYTES + row * 48 + seg * 16;
    }

    // ldmatrix per-lane offsets
    // A (X region): row = lane&15, col-half = lane>>4
    unsigned offA = (unsigned)((lane & 15) * 48 + (lane >> 4) * 16);
    // B (W region): row = ((lane>>4)&1)*8 + (lane&7), k-half = (lane>>3)&1
    unsigned offB = (unsigned)((((lane >> 4) & 1) * 8 + (lane & 7)) * 48 + ((lane >> 3) & 1) * 16);
    unsigned aAddr0 = smbase + W_BYTES + (wm * 32) * 48 + offA;        // mt=0
    unsigned aAddr1 = aAddr0 + 16 * 48;                                 // mt=1
    unsigned bAddr0 = smbase + (wj * 32) * 48 + offB;                   // pair 0 (nt0,1)
    unsigned bAddr1 = bAddr0 + 16 * 48;                                 // pair 1 (nt2,3)

    float acc[2][4][4];
    #pragma unroll
    for (int a = 0; a < 2; a++)
        #pragma unroll
        for (int b = 0; b < 4; b++)
            #pragma unroll
            for (int q = 0; q < 4; q++) acc[a][b][q] = 0.f;

    // prologue: load iter-0 data into registers
    float4 w0 = *(const float4*)(wsrc[0]);
    float4 w1 = *(const float4*)(wsrc[1]);
    uint4  x0 = xload ? *(const uint4*)(xsrc) : make_uint4(0, 0, 0, 0);

    for (int it = 0; it < iters; it++) {
        unsigned st = (unsigned)(it & 1) * STG_B;

        // STS: convert W to bf16 (8B each), copy X (16B)
        {
            __nv_bfloat162 p0 = __floats2bfloat162_rn(w0.x, w0.y);
            __nv_bfloat162 p1 = __floats2bfloat162_rn(w0.z, w0.w);
            uint2 pk0 = make_uint2(*(unsigned*)&p0, *(unsigned*)&p1);
            __nv_bfloat162 p2 = __floats2bfloat162_rn(w1.x, w1.y);
            __nv_bfloat162 p3 = __floats2bfloat162_rn(w1.z, w1.w);
            uint2 pk1 = make_uint2(*(unsigned*)&p2, *(unsigned*)&p3);
            asm volatile("st.shared.v2.b32 [%0], {%1,%2};" :: "r"(wdst[0] + st), "r"(pk0.x), "r"(pk0.y));
            asm volatile("st.shared.v2.b32 [%0], {%1,%2};" :: "r"(wdst[1] + st), "r"(pk1.x), "r"(pk1.y));
            if (xload)
                asm volatile("st.shared.v4.b32 [%0], {%1,%2,%3,%4};"
                             :: "r"(xdst + st), "r"(x0.x), "r"(x0.y), "r"(x0.z), "r"(x0.w));
        }
        __syncthreads();

        // prefetch next iteration (latency hidden by this iteration's MMA)
        if (it + 1 < iters) {
            int ko = (it + 1) * BK1;
            w0 = *(const float4*)(wsrc[0] + ko);
            w1 = *(const float4*)(wsrc[1] + ko);
            if (xload) x0 = *(const uint4*)(xsrc + ko);
        }

        // fragments via ldmatrix + 8 MMAs
        unsigned a0[2], a1[2], a2[2], a3[2];
        ldsm4(a0[0], a1[0], a2[0], a3[0], aAddr0 + st);
        ldsm4(a0[1], a1[1], a2[1], a3[1], aAddr1 + st);
        unsigned b00, b01, b10, b11;
        ldsm4(b00, b01, b10, b11, bAddr0 + st);   // nt0: b00,b01  nt1: b10,b11
        #pragma unroll
        for (int mt = 0; mt < 2; mt++) {
            mma16816(acc[mt][0], a0[mt], a1[mt], a2[mt], a3[mt], b00, b01);
            mma16816(acc[mt][1], a0[mt], a1[mt], a2[mt], a3[mt], b10, b11);
        }
        ldsm4(b00, b01, b10, b11, bAddr1 + st);   // nt2, nt3
        #pragma unroll
        for (int mt = 0; mt < 2; mt++) {
            mma16816(acc[mt][2], a0[mt], a1[mt], a2[mt], a3[mt], b00, b01);
            mma16816(acc[mt][3], a0[mt], a1[mt], a2[mt], a3[mt], b10, b11);
        }
    }

    // epilogue: plain STG into split-private partials
    float* hp = &g_hpart[blockIdx.y][0][0];
    #pragma unroll
    for (int mt = 0; mt < 2; mt++) {
        #pragma unroll
        for (int nt = 0; nt < 4; nt++) {
            int m = wm * 32 + mt * 16 + gi;
            int j = jbase + wj * 32 + nt * 8 + qi * 2;
            if (j < Hh) {
                *(float2*)(hp + (size_t)m * Hh + j) =
                    make_float2(acc[mt][nt][0], acc[mt][nt][1]);
                *(float2*)(hp + (size_t)(m + 8) * Hh + j) =
                    make_float2(acc[mt][nt][2], acc[mt][nt][3]);
            }
        }
    }
}

// ---------------------------------------------------------------------------
// GEMM2 + split-reduce + bias + relu.  grid (64, 4), 256 thr.
// ---------------------------------------------------------------------------
__global__ void k_gemm2(const float* __restrict__ b1, const float* __restrict__ W2) {
    int m = blockIdx.x, q = blockIdx.y, tid = threadIdx.x;
    int jq = q * (Hh / 4);
    float s = 0.f;
    for (int t = tid * 4; t < Hh / 4; t += 1024) {
        int j = jq + t;
        float4 hs = make_float4(0.f, 0.f, 0.f, 0.f);
        #pragma unroll
        for (int sp = 0; sp < KSPLIT; sp++) {
            float4 hv = *(const float4*)(&g_hpart[sp][m][j]);
            hs.x += hv.x; hs.y += hv.y; hs.z += hv.z; hs.w += hv.w;
        }
        float4 bv = *(const float4*)(b1 + j);
        float4 wv = *(const float4*)(W2 + j);
        s += fmaxf(hs.x + bv.x, 0.f) * wv.x;
        s += fmaxf(hs.y + bv.y, 0.f) * wv.y;
        s += fmaxf(hs.z + bv.z, 0.f) * wv.z;
        s += fmaxf(hs.w + bv.w, 0.f) * wv.w;
    }
    #pragma unroll
    for (int o = 16; o > 0; o >>= 1) s += __shfl_down_sync(0xffffffffu, s, o);
    __shared__ float red[8];
    if ((tid & 31) == 0) red[tid >> 5] = s;
    __syncthreads();
    if (tid < 8) {
        s = red[tid];
        #pragma unroll
        for (int o = 4; o > 0; o >>= 1) s += __shfl_down_sync(0xffu, s, o);
        if (tid == 0) g_l2[m * 4 + q] = s;
    }
}

// ---------------------------------------------------------------------------
// Loss
// ---------------------------------------------------------------------------
__global__ void k_loss(const float* __restrict__ b2, float* __restrict__ out) {
    int tid = threadIdx.x;  // 64 threads
    float l = g_l2[tid * 4] + g_l2[tid * 4 + 1] + g_l2[tid * 4 + 2] + g_l2[tid * 4 + 3] + b2[0];
    float per = (l > 0.f) ? log1pf(expf(-l)) : (log1pf(expf(l)) - l);
    #pragma unroll
    for (int o = 16; o > 0; o >>= 1) per += __shfl_down_sync(0xffffffffu, per, o);
    __shared__ float r2[2];
    if ((tid & 31) == 0) r2[tid >> 5] = per;
    __syncthreads();
    if (tid == 0) out[0] = (r2[0] + r2[1]) * (1.0f / Bb);
}

// ---------------------------------------------------------------------------
extern "C" void kernel_launch(void* const* d_in, const int* in_sizes, int n_in,
                              void* d_out, int out_size) {
    const float* feat     = (const float*)d_in[0];
    const float* w        = (const float*)d_in[3];
    const float* bn_gamma = (const float*)d_in[4];
    const float* bn_beta  = (const float*)d_in[5];
    const float* bn_mean  = (const float*)d_in[6];
    const float* bn_var   = (const float*)d_in[7];
    const float* W1       = (const float*)d_in[8];
    const float* b1       = (const float*)d_in[9];
    const float* W2       = (const float*)d_in[10];
    const float* b2       = (const float*)d_in[11];

    k_sort<<<Bb, 512>>>(feat, w);
    dim3 gbn(Bb, 4);
    k_bn<<<gbn, 256>>>(feat, bn_mean, bn_var, bn_gamma, bn_beta);
    dim3 g1(63, KSPLIT);   // 441 CTAs, 3/SM -> one wave
    k_gemm1<<<g1, 256>>>(W1);
    dim3 g2(Bb, 4);
    k_gemm2<<<g2, 256>>>(b1, W2);
    k_loss<<<1, 64>>>(b2, (float*)d_out);
}

// round 8
// speedup vs baseline: 1.7329x; 1.0667x over previous
#include <cuda_runtime.h>
#include <cuda_bf16.h>
#include <math.h>
#include <stdint.h>

// Problem constants
#define Bb   64
#define NPG  400
#define Kk   250
#define Ff   64
#define LIN  16000
#define Hh   8000
#define Nn   (Bb*NPG)        // 25600
#define BN_EPS 1e-5f

#define KSPLIT 7
#define KCH    2304          // 6 chunks of 2304 + 1 of 2176 = 16000 (both /32)
#define G2SPLIT 16

// Scratch (device globals; no allocation allowed)
__device__ __nv_bfloat16 g_xb[Bb*LIN];      // bf16 normalized features
__device__ int   g_selidx[Bb*Kk];
__device__ float g_stanh[Bb*Kk];
__device__ float g_hpart[KSPLIT][Bb][Hh];   // split-K partials
__device__ float g_l2[Bb*G2SPLIT];          // gemm2 partial logits

// ---------------------------------------------------------------------------
// Kernel: fused scores + bitonic top-K; writes selected idx + tanh(score)
// ---------------------------------------------------------------------------
__global__ void k_sort(const float* __restrict__ feat, const float* __restrict__ w) {
    __shared__ float sv[512];
    __shared__ int   si[512];
    __shared__ float s_inv;
    int tid = threadIdx.x, b = blockIdx.x;
    int warp = tid >> 5, lane = tid & 31;

    if (tid == 0) {
        float s = 0.f;
        #pragma unroll
        for (int i = 0; i < Ff; i++) s += w[i] * w[i];
        s_inv = rsqrtf(s);
    }
    const float* xg = feat + (size_t)11 * Nn * Ff + (size_t)b * NPG * Ff;
    float wl0 = w[lane], wl1 = w[lane + 32];
    for (int nd = warp; nd < NPG; nd += 16) {
        const float* x = xg + (size_t)nd * Ff;
        float v = x[lane] * wl0 + x[lane + 32] * wl1;
        #pragma unroll
        for (int o = 16; o > 0; o >>= 1) v += __shfl_down_sync(0xffffffffu, v, o);
        if (lane == 0) sv[nd] = v;
    }
    if (tid >= NPG) sv[tid] = __int_as_float(0xff800000);
    si[tid] = tid;
    __syncthreads();

    for (int k = 2; k <= 512; k <<= 1) {
        for (int j = k >> 1; j > 0; j >>= 1) {
            int ixj = tid ^ j;
            if (ixj > tid) {
                float va = sv[tid], vb = sv[ixj];
                int   ia = si[tid], ib = si[ixj];
                bool aFirst = (va > vb) || (va == vb && ia < ib);
                bool bFirst = (vb > va) || (vb == va && ib < ia);
                bool desc = ((tid & k) == 0);
                bool sw = desc ? bFirst : aFirst;
                if (sw) { sv[tid] = vb; sv[ixj] = va; si[tid] = ib; si[ixj] = ia; }
            }
            __syncthreads();
        }
    }
    if (tid < Kk) {
        g_selidx[b * Kk + tid] = si[tid];
        g_stanh[b * Kk + tid]  = tanhf(sv[tid] * s_inv);
    }
}

// ---------------------------------------------------------------------------
// Kernel: gather + BatchNorm -> bf16 xn   grid (64, 4)
// ---------------------------------------------------------------------------
__global__ void k_bn(const float* __restrict__ feat,
                     const float* __restrict__ bn_mean, const float* __restrict__ bn_var,
                     const float* __restrict__ bn_gamma, const float* __restrict__ bn_beta) {
    int b = blockIdx.x, q = blockIdx.y, tid = threadIdx.x;
    const float* xg = feat + (size_t)11 * Nn * Ff + (size_t)b * NPG * Ff;
    int base = q * (LIN / 4);
    for (int t = tid; t < LIN / 4; t += 256) {
        int i = base + t;
        int r = i >> 6, f = i & 63;
        int idx = g_selidx[b * Kk + r];
        float st = g_stanh[b * Kk + r];
        float xv = xg[idx * Ff + f];
        float xn = (xv * st - bn_mean[i]) * rsqrtf(bn_var[i] + BN_EPS) * bn_gamma[i] + bn_beta[i];
        g_xb[(size_t)b * LIN + i] = __float2bfloat16(xn);
    }
}

// ---------------------------------------------------------------------------
// GEMM1:  hpart[s][m][j] = sum_{k in chunk s} xn[m,k] * W1[j,k]
// bf16 mma.sync m16n8k16, W fp32->bf16 in-register, ldmatrix fragments.
// Block 256 thr (8 warps), warp tile 32m x 32j, BK=32, 2-stage smem,
// 3 CTAs/SM. grid (63, 7) = 441 CTAs = one wave.
// ---------------------------------------------------------------------------
#define BN1   128
#define BK1   32
#define ROWB  80                    // bytes per smem row (40 halves)
#define W_BYTES (128 * ROWB)        // 10240
#define X_BYTES (64 * ROWB)         // 5120
#define STG_B   (W_BYTES + X_BYTES) // 15360

__device__ __forceinline__ void mma16816(float* d,
                                         unsigned a0, unsigned a1, unsigned a2, unsigned a3,
                                         unsigned b0, unsigned b1) {
    asm volatile(
        "mma.sync.aligned.m16n8k16.row.col.f32.bf16.bf16.f32 "
        "{%0,%1,%2,%3}, {%4,%5,%6,%7}, {%8,%9}, {%0,%1,%2,%3};\n"
        : "+f"(d[0]), "+f"(d[1]), "+f"(d[2]), "+f"(d[3])
        : "r"(a0), "r"(a1), "r"(a2), "r"(a3), "r"(b0), "r"(b1));
}

__device__ __forceinline__ void ldsm4(unsigned& r0, unsigned& r1, unsigned& r2, unsigned& r3,
                                      unsigned addr) {
    asm volatile("ldmatrix.sync.aligned.m8n8.x4.shared.b16 {%0,%1,%2,%3}, [%4];"
                 : "=r"(r0), "=r"(r1), "=r"(r2), "=r"(r3) : "r"(addr));
}

__global__ __launch_bounds__(256, 3) void k_gemm1(const float* __restrict__ W1) {
    __shared__ __align__(16) unsigned char sm[2 * STG_B];
    unsigned smbase = (unsigned)__cvta_generic_to_shared(sm);

    int tid  = threadIdx.x;
    int warp = tid >> 5, lane = tid & 31;
    int wm = warp >> 2, wj = warp & 3;
    int gi = lane >> 2, qi = lane & 3;
    int jbase = blockIdx.x * BN1;
    int kbase = blockIdx.y * KCH;
    int iters = (blockIdx.y == KSPLIT - 1) ? 68 : 72;   // 68*32=2176, 72*32=2304

    // W load mapping: 4 float4/thread. chunk c = tid + i*256: row=c>>3, c8=c&7
    const float* wsrc[4]; unsigned wdst[4];
    #pragma unroll
    for (int i = 0; i < 4; i++) {
        int c = tid + i * 256;
        int row = c >> 3, c8 = c & 7;
        int j = jbase + row; if (j > Hh - 1) j = Hh - 1;
        wsrc[i] = W1 + (size_t)j * LIN + kbase + c8 * 4;
        wdst[i] = smbase + row * ROWB + c8 * 8;
    }
    // X load mapping: all 256 threads, 1 uint4 (8 halves). row=tid>>2, seg=tid&3
    const __nv_bfloat16* xsrc; unsigned xdst;
    {
        int row = tid >> 2, seg = tid & 3;
        xsrc = g_xb + (size_t)row * LIN + kbase + seg * 8;
        xdst = smbase + W_BYTES + row * ROWB + seg * 16;
    }

    // ldmatrix per-lane offsets (row stride 80B; conflict-free)
    unsigned offA = (unsigned)((lane & 15) * ROWB + (lane >> 4) * 16);
    unsigned offB = (unsigned)((((lane >> 4) & 1) * 8 + (lane & 7)) * ROWB + ((lane >> 3) & 1) * 16);
    unsigned aAddr0 = smbase + W_BYTES + (wm * 32) * ROWB + offA;       // mt=0
    unsigned aAddr1 = aAddr0 + 16 * ROWB;                                // mt=1
    unsigned bAddr0 = smbase + (wj * 32) * ROWB + offB;                  // nt pair 0
    unsigned bAddr1 = bAddr0 + 16 * ROWB;                                // nt pair 1

    float acc[2][4][4];
    #pragma unroll
    for (int a = 0; a < 2; a++)
        #pragma unroll
        for (int b = 0; b < 4; b++)
            #pragma unroll
            for (int q = 0; q < 4; q++) acc[a][b][q] = 0.f;

    // prologue: iter-0 data into registers
    float4 wv[4];
    #pragma unroll
    for (int i = 0; i < 4; i++) wv[i] = *(const float4*)(wsrc[i]);
    uint4 x0 = *(const uint4*)(xsrc);

    for (int it = 0; it < iters; it++) {
        unsigned st = (unsigned)(it & 1) * STG_B;

        // STS: convert W to bf16 (8B each), copy X (16B)
        #pragma unroll
        for (int i = 0; i < 4; i++) {
            __nv_bfloat162 p0 = __floats2bfloat162_rn(wv[i].x, wv[i].y);
            __nv_bfloat162 p1 = __floats2bfloat162_rn(wv[i].z, wv[i].w);
            asm volatile("st.shared.v2.b32 [%0], {%1,%2};"
                         :: "r"(wdst[i] + st), "r"(*(unsigned*)&p0), "r"(*(unsigned*)&p1));
        }
        asm volatile("st.shared.v4.b32 [%0], {%1,%2,%3,%4};"
                     :: "r"(xdst + st), "r"(x0.x), "r"(x0.y), "r"(x0.z), "r"(x0.w));
        __syncthreads();

        // prefetch next iteration (hidden under this iteration's MMAs)
        if (it + 1 < iters) {
            int ko = (it + 1) * BK1;
            #pragma unroll
            for (int i = 0; i < 4; i++) wv[i] = *(const float4*)(wsrc[i] + ko);
            x0 = *(const uint4*)(xsrc + ko);
        }

        // two k16 sub-chunks
        #pragma unroll
        for (int kk = 0; kk < 2; kk++) {
            unsigned ko = (unsigned)(kk * 32);   // 16 halves = 32B
            unsigned a0[2], a1[2], a2[2], a3[2];
            ldsm4(a0[0], a1[0], a2[0], a3[0], aAddr0 + st + ko);
            ldsm4(a0[1], a1[1], a2[1], a3[1], aAddr1 + st + ko);
            unsigned b00, b01, b10, b11;
            ldsm4(b00, b01, b10, b11, bAddr0 + st + ko);
            #pragma unroll
            for (int mt = 0; mt < 2; mt++) {
                mma16816(acc[mt][0], a0[mt], a1[mt], a2[mt], a3[mt], b00, b01);
                mma16816(acc[mt][1], a0[mt], a1[mt], a2[mt], a3[mt], b10, b11);
            }
            ldsm4(b00, b01, b10, b11, bAddr1 + st + ko);
            #pragma unroll
            for (int mt = 0; mt < 2; mt++) {
                mma16816(acc[mt][2], a0[mt], a1[mt], a2[mt], a3[mt], b00, b01);
                mma16816(acc[mt][3], a0[mt], a1[mt], a2[mt], a3[mt], b10, b11);
            }
        }
        __syncthreads();
    }

    // epilogue: plain STG into split-private partials
    float* hp = &g_hpart[blockIdx.y][0][0];
    #pragma unroll
    for (int mt = 0; mt < 2; mt++) {
        #pragma unroll
        for (int nt = 0; nt < 4; nt++) {
            int m = wm * 32 + mt * 16 + gi;
            int j = jbase + wj * 32 + nt * 8 + qi * 2;
            if (j < Hh) {
                *(float2*)(hp + (size_t)m * Hh + j) =
                    make_float2(acc[mt][nt][0], acc[mt][nt][1]);
                *(float2*)(hp + (size_t)(m + 8) * Hh + j) =
                    make_float2(acc[mt][nt][2], acc[mt][nt][3]);
            }
        }
    }
}

// ---------------------------------------------------------------------------
// GEMM2 + split-reduce + bias + relu.  grid (64, 16), 256 thr.
// ---------------------------------------------------------------------------
__global__ void k_gemm2(const float* __restrict__ b1, const float* __restrict__ W2) {
    int m = blockIdx.x, q = blockIdx.y, tid = threadIdx.x;
    int jq = q * (Hh / G2SPLIT);          // 500 per split
    float s = 0.f;
    for (int t = tid * 4; t < Hh / G2SPLIT; t += 1024) {
        int j = jq + t;
        float4 hs = make_float4(0.f, 0.f, 0.f, 0.f);
        #pragma unroll
        for (int sp = 0; sp < KSPLIT; sp++) {
            float4 hv = *(const float4*)(&g_hpart[sp][m][j]);
            hs.x += hv.x; hs.y += hv.y; hs.z += hv.z; hs.w += hv.w;
        }
        float4 bv = *(const float4*)(b1 + j);
        float4 wv = *(const float4*)(W2 + j);
        s += fmaxf(hs.x + bv.x, 0.f) * wv.x;
        s += fmaxf(hs.y + bv.y, 0.f) * wv.y;
        s += fmaxf(hs.z + bv.z, 0.f) * wv.z;
        s += fmaxf(hs.w + bv.w, 0.f) * wv.w;
    }
    #pragma unroll
    for (int o = 16; o > 0; o >>= 1) s += __shfl_down_sync(0xffffffffu, s, o);
    __shared__ float red[8];
    if ((tid & 31) == 0) red[tid >> 5] = s;
    __syncthreads();
    if (tid < 8) {
        s = red[tid];
        #pragma unroll
        for (int o = 4; o > 0; o >>= 1) s += __shfl_down_sync(0xffu, s, o);
        if (tid == 0) g_l2[m * G2SPLIT + q] = s;
    }
}

// ---------------------------------------------------------------------------
// Loss
// ---------------------------------------------------------------------------
__global__ void k_loss(const float* __restrict__ b2, float* __restrict__ out) {
    int tid = threadIdx.x;  // 64 threads
    float l = b2[0];
    #pragma unroll
    for (int q = 0; q < G2SPLIT; q++) l += g_l2[tid * G2SPLIT + q];
    float per = (l > 0.f) ? log1pf(expf(-l)) : (log1pf(expf(l)) - l);
    #pragma unroll
    for (int o = 16; o > 0; o >>= 1) per += __shfl_down_sync(0xffffffffu, per, o);
    __shared__ float r2[2];
    if ((tid & 31) == 0) r2[tid >> 5] = per;
    __syncthreads();
    if (tid == 0) out[0] = (r2[0] + r2[1]) * (1.0f / Bb);
}

// ---------------------------------------------------------------------------
extern "C" void kernel_launch(void* const* d_in, const int* in_sizes, int n_in,
                              void* d_out, int out_size) {
    const float* feat     = (const float*)d_in[0];
    const float* w        = (const float*)d_in[3];
    const float* bn_gamma = (const float*)d_in[4];
    const float* bn_beta  = (const float*)d_in[5];
    const float* bn_mean  = (const float*)d_in[6];
    const float* bn_var   = (const float*)d_in[7];
    const float* W1       = (const float*)d_in[8];
    const float* b1       = (const float*)d_in[9];
    const float* W2       = (const float*)d_in[10];
    const float* b2       = (const float*)d_in[11];

    k_sort<<<Bb, 512>>>(feat, w);
    dim3 gbn(Bb, 4);
    k_bn<<<gbn, 256>>>(feat, bn_mean, bn_var, bn_gamma, bn_beta);
    dim3 g1(63, KSPLIT);   // 441 CTAs, 3/SM -> one wave
    k_gemm1<<<g1, 256>>>(W1);
    dim3 g2(Bb, G2SPLIT);
    k_gemm2<<<g2, 256>>>(b1, W2);
    k_loss<<<1, 64>>>(b2, (float*)d_out);
}